// round 3
// baseline (speedup 1.0000x reference)
#include <cuda_runtime.h>
#include <cuda_bf16.h>

// Problem constants
#define BB 4
#define SS 2048
#define EE 1024
#define HH 16
#define HD 64
#define E3 (3 * EE)

// Scratch (alloc-free requirement -> __device__ globals, referenced directly
// from kernels so kernel_launch contains ONLY kernel launches)
__device__ float g_qkv[BB * SS * E3];      // [b, s, 3E]  (~100 MB)
__device__ float g_attn[BB * SS * EE];     // [b, s, E]   (~33 MB)

// ---------------------------------------------------------------------------
// SGEMM with fused bias: C[M,N] = A[M,K] @ B[K,N] + bias[N]
// BM=BN=128, BK=8, TM=TN=8, 256 threads. All dims divisible by tiles.
// ---------------------------------------------------------------------------
template <bool A_SCRATCH_ATTN, bool C_SCRATCH_QKV>
__global__ __launch_bounds__(256)
void sgemm_bias(int M, int N, int K,
                const float* __restrict__ Ain,
                const float* __restrict__ B,
                const float* __restrict__ bias,
                float* __restrict__ Cout) {
    constexpr int BM = 128, BN = 128, BK = 8, TM = 8, TN = 8;
    const float* A = A_SCRATCH_ATTN ? g_attn : Ain;
    float* C = C_SCRATCH_QKV ? g_qkv : Cout;

    const int cRow = blockIdx.y;
    const int cCol = blockIdx.x;
    const int tid = threadIdx.x;

    __shared__ float As[BK * BM];   // transposed: As[k*BM + m]
    __shared__ float Bs[BK * BN];

    A += cRow * BM * K;
    B += cCol * BN;

    const int innerRowA = tid >> 1;        // 0..127
    const int innerColA = (tid & 1) * 4;   // 0 or 4
    const int innerRowB = tid >> 5;        // 0..7 (k)
    const int innerColB = (tid & 31) * 4;  // 0..124
    const int threadCol = tid & 15;        // 0..15
    const int threadRow = tid >> 4;        // 0..15

    float acc[TM * TN] = {0.0f};
    float regM[TM], regN[TN];

    for (int bk = 0; bk < K; bk += BK) {
        float4 ta = *reinterpret_cast<const float4*>(&A[innerRowA * K + innerColA]);
        As[(innerColA + 0) * BM + innerRowA] = ta.x;
        As[(innerColA + 1) * BM + innerRowA] = ta.y;
        As[(innerColA + 2) * BM + innerRowA] = ta.z;
        As[(innerColA + 3) * BM + innerRowA] = ta.w;
        *reinterpret_cast<float4*>(&Bs[innerRowB * BN + innerColB]) =
            *reinterpret_cast<const float4*>(&B[innerRowB * N + innerColB]);
        __syncthreads();
        A += BK;
        B += BK * N;
#pragma unroll
        for (int k = 0; k < BK; ++k) {
#pragma unroll
            for (int i = 0; i < TM; ++i) regM[i] = As[k * BM + threadRow * TM + i];
#pragma unroll
            for (int i = 0; i < TN; ++i) regN[i] = Bs[k * BN + threadCol * TN + i];
#pragma unroll
            for (int m = 0; m < TM; ++m)
#pragma unroll
                for (int n = 0; n < TN; ++n)
                    acc[m * TN + n] += regM[m] * regN[n];
        }
        __syncthreads();
    }

#pragma unroll
    for (int m = 0; m < TM; ++m) {
        int row = cRow * BM + threadRow * TM + m;
#pragma unroll
        for (int n = 0; n < TN; n += 4) {
            int col = cCol * BN + threadCol * TN + n;
            float4 b4 = *reinterpret_cast<const float4*>(&bias[col]);
            float4 r;
            r.x = acc[m * TN + n + 0] + b4.x;
            r.y = acc[m * TN + n + 1] + b4.y;
            r.z = acc[m * TN + n + 2] + b4.z;
            r.w = acc[m * TN + n + 3] + b4.w;
            *reinterpret_cast<float4*>(&C[row * N + col]) = r;
        }
    }
}

// ---------------------------------------------------------------------------
// fp32 flash attention over qkv scratch.
// Grid: (S/BR, H, B). Block: 256 threads = 8 warps.
// Each warp owns 4 query rows; each row handled by 8 lanes (8 dims each).
// Key tiles of BC=64 staged in shared memory. Causal tiles skipped.
// RACE FIX: barrier moved to AFTER the P*V accumulation (Vs reads must be
// fenced against the next tile's cooperative load).
// ---------------------------------------------------------------------------
#define BR 32
#define BC 64

__global__ __launch_bounds__(256)
void flash_attn(const int* __restrict__ amask) {
    const float* qkv = g_qkv;
    float* out = g_attn;

    const int qblk = blockIdx.x;
    const int h = blockIdx.y;
    const int b = blockIdx.z;
    const int tid = threadIdx.x;
    const int warp = tid >> 5;
    const int lane = tid & 31;
    const int rloc = warp * 4 + (lane >> 3);     // 0..31 row within block
    const int qrow = qblk * BR + rloc;
    const int chunk = lane & 7;                  // dim group: chunk*8 .. chunk*8+7

    __shared__ float Ks[BC][HD];
    __shared__ float Vs[BC][HD];
    __shared__ int Ms[BC];

    const int base = b * SS * E3;

    // Load this lane's Q fragment (8 dims)
    const float* qp = qkv + (b * SS + qrow) * E3 + h * HD + chunk * 8;
    float4 q0 = *reinterpret_cast<const float4*>(qp);
    float4 q1 = *reinterpret_cast<const float4*>(qp + 4);

    float o[8] = {0.f, 0.f, 0.f, 0.f, 0.f, 0.f, 0.f, 0.f};
    float mrun = -1e30f, lrun = 0.f;
    const float scale = 0.125f;   // 1/sqrt(64)

    const int ktmax = (qblk * BR + BR - 1) / BC;   // last tile containing needed keys

    for (int kt = 0; kt <= ktmax; ++kt) {
        const int k0 = kt * BC;
        // Cooperative K/V tile load: 64 rows x 16 float4 each
        for (int i = tid; i < BC * 16; i += 256) {
            int r = i >> 4;
            int c4 = (i & 15) * 4;
            const float* kp = qkv + base + (k0 + r) * E3 + EE + h * HD + c4;
            const float* vp = qkv + base + (k0 + r) * E3 + 2 * EE + h * HD + c4;
            *reinterpret_cast<float4*>(&Ks[r][c4]) = *reinterpret_cast<const float4*>(kp);
            *reinterpret_cast<float4*>(&Vs[r][c4]) = *reinterpret_cast<const float4*>(vp);
        }
        if (tid < BC) Ms[tid] = amask[b * SS + k0 + tid];
        __syncthreads();

        float s[BC];
#pragma unroll
        for (int c = 0; c < BC; ++c) {
            float4 ka = *reinterpret_cast<const float4*>(&Ks[c][chunk * 8]);
            float4 kb = *reinterpret_cast<const float4*>(&Ks[c][chunk * 8 + 4]);
            float acc = q0.x * ka.x + q0.y * ka.y + q0.z * ka.z + q0.w * ka.w
                      + q1.x * kb.x + q1.y * kb.y + q1.z * kb.z + q1.w * kb.w;
            // reduce across the 8 lanes of this row (xor within low 3 bits)
            acc += __shfl_xor_sync(0xFFFFFFFFu, acc, 4);
            acc += __shfl_xor_sync(0xFFFFFFFFu, acc, 2);
            acc += __shfl_xor_sync(0xFFFFFFFFu, acc, 1);
            int kcol = k0 + c;
            bool valid = (kcol <= qrow) && (Ms[c] != 0);
            s[c] = valid ? acc * scale : -1e30f;
        }

        float mt = s[0];
#pragma unroll
        for (int c = 1; c < BC; ++c) mt = fmaxf(mt, s[c]);
        float mnew = fmaxf(mrun, mt);
        float alpha = __expf(mrun - mnew);
        float lsum = 0.f;
#pragma unroll
        for (int c = 0; c < BC; ++c) {
            float p = __expf(s[c] - mnew);
            s[c] = p;
            lsum += p;
        }
        lrun = lrun * alpha + lsum;
#pragma unroll
        for (int j = 0; j < 8; ++j) o[j] *= alpha;
#pragma unroll
        for (int c = 0; c < BC; ++c) {
            float p = s[c];
            float4 va = *reinterpret_cast<const float4*>(&Vs[c][chunk * 8]);
            float4 vb = *reinterpret_cast<const float4*>(&Vs[c][chunk * 8 + 4]);
            o[0] += p * va.x; o[1] += p * va.y; o[2] += p * va.z; o[3] += p * va.w;
            o[4] += p * vb.x; o[5] += p * vb.y; o[6] += p * vb.z; o[7] += p * vb.w;
        }
        mrun = mnew;
        __syncthreads();   // fence Ks/Vs/Ms reads against next tile's overwrite
    }

    const float inv = 1.0f / lrun;
    float* op = out + (b * SS + qrow) * EE + h * HD + chunk * 8;
    float4 r0, r1;
    r0.x = o[0] * inv; r0.y = o[1] * inv; r0.z = o[2] * inv; r0.w = o[3] * inv;
    r1.x = o[4] * inv; r1.y = o[5] * inv; r1.z = o[6] * inv; r1.w = o[7] * inv;
    *reinterpret_cast<float4*>(op) = r0;
    *reinterpret_cast<float4*>(op + 4) = r1;
}

// ---------------------------------------------------------------------------
// Launch — ONLY kernel launches (no runtime API calls in the capture path)
// ---------------------------------------------------------------------------
extern "C" void kernel_launch(void* const* d_in, const int* in_sizes, int n_in,
                              void* d_out, int out_size) {
    const float* x      = (const float*)d_in[0];
    const int*   amask  = (const int*)d_in[1];
    const float* W_attn = (const float*)d_in[2];
    const float* b_attn = (const float*)d_in[3];
    const float* W_proj = (const float*)d_in[4];
    const float* b_proj = (const float*)d_in[5];
    float* out = (float*)d_out;

    // 1) QKV projection: [8192,1024] @ [1024,3072] + bias -> g_qkv
    {
        dim3 grid(E3 / 128, (BB * SS) / 128);
        sgemm_bias<false, true><<<grid, 256>>>(BB * SS, E3, EE, x, W_attn, b_attn, nullptr);
    }
    // 2) Attention: g_qkv -> g_attn
    {
        dim3 grid(SS / BR, HH, BB);
        flash_attn<<<grid, 256>>>(amask);
    }
    // 3) Output projection: [8192,1024] @ [1024,1024] + bias -> d_out
    {
        dim3 grid(EE / 128, (BB * SS) / 128);
        sgemm_bias<true, false><<<grid, 256>>>(BB * SS, EE, EE, nullptr, W_proj, b_proj, out);
    }
}

// round 4
// speedup vs baseline: 1.1785x; 1.1785x over previous
#include <cuda_runtime.h>
#include <cuda_bf16.h>
#include <cstdint>

// Problem constants
#define BB 4
#define SS 2048
#define EE 1024
#define HH 16
#define HD 64
#define E3 (3 * EE)

// Scratch (alloc-free requirement -> __device__ globals)
__device__ float g_qkv[BB * SS * E3];      // [b, s, 3E]  (~100 MB)
__device__ float g_attn[BB * SS * EE];     // [b, s, E]   (~33 MB)

// ---------------------------------------------------------------------------
// tf32 helpers
// ---------------------------------------------------------------------------
__device__ __forceinline__ float f2tf32(float x) {
    uint32_t u;
    asm("cvt.rna.tf32.f32 %0, %1;" : "=r"(u) : "f"(x));
    return __uint_as_float(u);
}

__device__ __forceinline__ void mma_tf32(float* d, const uint32_t* a, const uint32_t* b) {
    asm volatile(
        "mma.sync.aligned.m16n8k8.row.col.f32.tf32.tf32.f32 "
        "{%0,%1,%2,%3}, {%4,%5,%6,%7}, {%8,%9}, {%0,%1,%2,%3};\n"
        : "+f"(d[0]), "+f"(d[1]), "+f"(d[2]), "+f"(d[3])
        : "r"(a[0]), "r"(a[1]), "r"(a[2]), "r"(a[3]), "r"(b[0]), "r"(b[1]));
}

// ---------------------------------------------------------------------------
// tf32 tensor-core GEMM with fused bias: C[M,N] = A[M,K] @ B[K,N] + bias[N]
// BM=BN=128, BK=16. 256 threads = 8 warps (2 x 4), warp tile 64x32.
// Each warp: 4 m-frags (m16) x 4 n-frags (n8), k split in 2 steps of 8.
// ---------------------------------------------------------------------------
#define GBM 128
#define GBN 128
#define GBK 16
#define APAD 4
#define BPAD 4

template <bool A_SCRATCH_ATTN, bool C_SCRATCH_QKV>
__global__ __launch_bounds__(256)
void gemm_tf32(int M, int N, int K,
               const float* __restrict__ Ain,
               const float* __restrict__ B,
               const float* __restrict__ bias,
               float* __restrict__ Cout) {
    const float* A = A_SCRATCH_ATTN ? g_attn : Ain;
    float* C = C_SCRATCH_QKV ? g_qkv : Cout;

    __shared__ float As[GBK][GBM + APAD];   // [k][m], tf32 bits
    __shared__ float Bs[GBK][GBN + BPAD];   // [k][n], tf32 bits

    const int tid  = threadIdx.x;
    const int warp = tid >> 5;
    const int lane = tid & 31;
    const int g    = lane >> 2;   // groupID 0..7
    const int t4   = lane & 3;    // threadID_in_group 0..3

    const int warpM = warp >> 2;  // 0..1 -> M offset *64
    const int warpN = warp & 3;   // 0..3 -> N offset *32

    const int blkM = blockIdx.y * GBM;
    const int blkN = blockIdx.x * GBN;

    // global loaders
    const int rA = tid >> 2;          // 0..63 (+64 for second)
    const int cA = (tid & 3) * 4;
    const int rB = tid >> 5;          // 0..7 (+8 for second)
    const int cB = (tid & 31) * 4;

    float acc[4][4][4];               // [mi][ni][4]
#pragma unroll
    for (int mi = 0; mi < 4; ++mi)
#pragma unroll
        for (int ni = 0; ni < 4; ++ni)
#pragma unroll
            for (int j = 0; j < 4; ++j) acc[mi][ni][j] = 0.f;

    for (int bk = 0; bk < K; bk += GBK) {
        // --- load A tile (transpose to [k][m], cvt tf32) ---
#pragma unroll
        for (int half = 0; half < 2; ++half) {
            int row = rA + half * 64;
            float4 a4 = *reinterpret_cast<const float4*>(&A[(blkM + row) * K + bk + cA]);
            As[cA + 0][row] = f2tf32(a4.x);
            As[cA + 1][row] = f2tf32(a4.y);
            As[cA + 2][row] = f2tf32(a4.z);
            As[cA + 3][row] = f2tf32(a4.w);
        }
        // --- load B tile ([k][n], cvt tf32) ---
#pragma unroll
        for (int half = 0; half < 2; ++half) {
            int row = rB + half * 8;
            float4 b4 = *reinterpret_cast<const float4*>(&B[(bk + row) * N + blkN + cB]);
            float4 t;
            t.x = f2tf32(b4.x); t.y = f2tf32(b4.y);
            t.z = f2tf32(b4.z); t.w = f2tf32(b4.w);
            *reinterpret_cast<float4*>(&Bs[row][cB]) = t;
        }
        __syncthreads();

#pragma unroll
        for (int ks = 0; ks < GBK; ks += 8) {
            // A fragments: a0 (g, t4) a1 (g+8, t4) a2 (g, t4+4) a3 (g+8, t4+4)
            uint32_t afrag[4][4];
#pragma unroll
            for (int mi = 0; mi < 4; ++mi) {
                int m0 = warpM * 64 + mi * 16 + g;
                afrag[mi][0] = __float_as_uint(As[ks + t4][m0]);
                afrag[mi][1] = __float_as_uint(As[ks + t4][m0 + 8]);
                afrag[mi][2] = __float_as_uint(As[ks + t4 + 4][m0]);
                afrag[mi][3] = __float_as_uint(As[ks + t4 + 4][m0 + 8]);
            }
            // B fragments: b0 (k=t4, n=g) b1 (k=t4+4, n=g)
            uint32_t bfrag[4][2];
#pragma unroll
            for (int ni = 0; ni < 4; ++ni) {
                int n0 = warpN * 32 + ni * 8 + g;
                bfrag[ni][0] = __float_as_uint(Bs[ks + t4][n0]);
                bfrag[ni][1] = __float_as_uint(Bs[ks + t4 + 4][n0]);
            }
#pragma unroll
            for (int mi = 0; mi < 4; ++mi)
#pragma unroll
                for (int ni = 0; ni < 4; ++ni)
                    mma_tf32(acc[mi][ni], afrag[mi], bfrag[ni]);
        }
        __syncthreads();
    }

    // --- epilogue: bias + store. c0,c1 -> (row g, cols 2t4,2t4+1); c2,c3 row g+8
#pragma unroll
    for (int mi = 0; mi < 4; ++mi) {
#pragma unroll
        for (int ni = 0; ni < 4; ++ni) {
            int row0 = blkM + warpM * 64 + mi * 16 + g;
            int col  = blkN + warpN * 32 + ni * 8 + 2 * t4;
            float2 b2 = *reinterpret_cast<const float2*>(&bias[col]);
            float2 r0, r1;
            r0.x = acc[mi][ni][0] + b2.x;
            r0.y = acc[mi][ni][1] + b2.y;
            r1.x = acc[mi][ni][2] + b2.x;
            r1.y = acc[mi][ni][3] + b2.y;
            *reinterpret_cast<float2*>(&C[row0 * N + col]) = r0;
            *reinterpret_cast<float2*>(&C[(row0 + 8) * N + col]) = r1;
        }
    }
}

// ---------------------------------------------------------------------------
// fp32 flash attention over qkv scratch (unchanged, known-good).
// Grid: (S/BR, H, B). Block: 256 threads = 8 warps.
// ---------------------------------------------------------------------------
#define BR 32
#define BC 64

__global__ __launch_bounds__(256)
void flash_attn(const int* __restrict__ amask) {
    const float* qkv = g_qkv;
    float* out = g_attn;

    const int qblk = blockIdx.x;
    const int h = blockIdx.y;
    const int b = blockIdx.z;
    const int tid = threadIdx.x;
    const int warp = tid >> 5;
    const int lane = tid & 31;
    const int rloc = warp * 4 + (lane >> 3);     // 0..31 row within block
    const int qrow = qblk * BR + rloc;
    const int chunk = lane & 7;                  // dim group: chunk*8 .. chunk*8+7

    __shared__ float Ks[BC][HD];
    __shared__ float Vs[BC][HD];
    __shared__ int Ms[BC];

    const int base = b * SS * E3;

    const float* qp = qkv + (b * SS + qrow) * E3 + h * HD + chunk * 8;
    float4 q0 = *reinterpret_cast<const float4*>(qp);
    float4 q1 = *reinterpret_cast<const float4*>(qp + 4);

    float o[8] = {0.f, 0.f, 0.f, 0.f, 0.f, 0.f, 0.f, 0.f};
    float mrun = -1e30f, lrun = 0.f;
    const float scale = 0.125f;   // 1/sqrt(64)

    const int ktmax = (qblk * BR + BR - 1) / BC;

    for (int kt = 0; kt <= ktmax; ++kt) {
        const int k0 = kt * BC;
        for (int i = tid; i < BC * 16; i += 256) {
            int r = i >> 4;
            int c4 = (i & 15) * 4;
            const float* kp = qkv + base + (k0 + r) * E3 + EE + h * HD + c4;
            const float* vp = qkv + base + (k0 + r) * E3 + 2 * EE + h * HD + c4;
            *reinterpret_cast<float4*>(&Ks[r][c4]) = *reinterpret_cast<const float4*>(kp);
            *reinterpret_cast<float4*>(&Vs[r][c4]) = *reinterpret_cast<const float4*>(vp);
        }
        if (tid < BC) Ms[tid] = amask[b * SS + k0 + tid];
        __syncthreads();

        float s[BC];
#pragma unroll
        for (int c = 0; c < BC; ++c) {
            float4 ka = *reinterpret_cast<const float4*>(&Ks[c][chunk * 8]);
            float4 kb = *reinterpret_cast<const float4*>(&Ks[c][chunk * 8 + 4]);
            float acc = q0.x * ka.x + q0.y * ka.y + q0.z * ka.z + q0.w * ka.w
                      + q1.x * kb.x + q1.y * kb.y + q1.z * kb.z + q1.w * kb.w;
            acc += __shfl_xor_sync(0xFFFFFFFFu, acc, 4);
            acc += __shfl_xor_sync(0xFFFFFFFFu, acc, 2);
            acc += __shfl_xor_sync(0xFFFFFFFFu, acc, 1);
            int kcol = k0 + c;
            bool valid = (kcol <= qrow) && (Ms[c] != 0);
            s[c] = valid ? acc * scale : -1e30f;
        }

        float mt = s[0];
#pragma unroll
        for (int c = 1; c < BC; ++c) mt = fmaxf(mt, s[c]);
        float mnew = fmaxf(mrun, mt);
        float alpha = __expf(mrun - mnew);
        float lsum = 0.f;
#pragma unroll
        for (int c = 0; c < BC; ++c) {
            float p = __expf(s[c] - mnew);
            s[c] = p;
            lsum += p;
        }
        lrun = lrun * alpha + lsum;
#pragma unroll
        for (int j = 0; j < 8; ++j) o[j] *= alpha;
#pragma unroll
        for (int c = 0; c < BC; ++c) {
            float p = s[c];
            float4 va = *reinterpret_cast<const float4*>(&Vs[c][chunk * 8]);
            float4 vb = *reinterpret_cast<const float4*>(&Vs[c][chunk * 8 + 4]);
            o[0] += p * va.x; o[1] += p * va.y; o[2] += p * va.z; o[3] += p * va.w;
            o[4] += p * vb.x; o[5] += p * vb.y; o[6] += p * vb.z; o[7] += p * vb.w;
        }
        mrun = mnew;
        __syncthreads();   // fence Ks/Vs/Ms reads against next tile's overwrite
    }

    const float inv = 1.0f / lrun;
    float* op = out + (b * SS + qrow) * EE + h * HD + chunk * 8;
    float4 r0, r1;
    r0.x = o[0] * inv; r0.y = o[1] * inv; r0.z = o[2] * inv; r0.w = o[3] * inv;
    r1.x = o[4] * inv; r1.y = o[5] * inv; r1.z = o[6] * inv; r1.w = o[7] * inv;
    *reinterpret_cast<float4*>(op) = r0;
    *reinterpret_cast<float4*>(op + 4) = r1;
}

// ---------------------------------------------------------------------------
// Launch — ONLY kernel launches
// ---------------------------------------------------------------------------
extern "C" void kernel_launch(void* const* d_in, const int* in_sizes, int n_in,
                              void* d_out, int out_size) {
    const float* x      = (const float*)d_in[0];
    const int*   amask  = (const int*)d_in[1];
    const float* W_attn = (const float*)d_in[2];
    const float* b_attn = (const float*)d_in[3];
    const float* W_proj = (const float*)d_in[4];
    const float* b_proj = (const float*)d_in[5];
    float* out = (float*)d_out;

    // 1) QKV projection: [8192,1024] @ [1024,3072] + bias -> g_qkv
    {
        dim3 grid(E3 / GBN, (BB * SS) / GBM);
        gemm_tf32<false, true><<<grid, 256>>>(BB * SS, E3, EE, x, W_attn, b_attn, nullptr);
    }
    // 2) Attention: g_qkv -> g_attn
    {
        dim3 grid(SS / BR, HH, BB);
        flash_attn<<<grid, 256>>>(amask);
    }
    // 3) Output projection: [8192,1024] @ [1024,1024] + bias -> d_out
    {
        dim3 grid(EE / GBN, (BB * SS) / GBM);
        gemm_tf32<true, false><<<grid, 256>>>(BB * SS, EE, EE, nullptr, W_proj, b_proj, out);
    }
}

// round 5
// speedup vs baseline: 5.1194x; 4.3440x over previous
#include <cuda_runtime.h>
#include <cuda_bf16.h>
#include <cstdint>

// Problem constants
#define BB 4
#define SS 2048
#define EE 1024
#define HH 16
#define HD 64
#define E3 (3 * EE)

// Scratch (alloc-free requirement -> __device__ globals)
__device__ float g_qkv[BB * SS * E3];      // [b, s, 3E]  (~100 MB)
__device__ float g_attn[BB * SS * EE];     // [b, s, E]   (~33 MB)

// ---------------------------------------------------------------------------
// helpers
// ---------------------------------------------------------------------------
__device__ __forceinline__ float f2tf32(float x) {
    uint32_t u;
    asm("cvt.rna.tf32.f32 %0, %1;" : "=r"(u) : "f"(x));
    return __uint_as_float(u);
}

__device__ __forceinline__ void mma_tf32(float* d, const uint32_t* a, const uint32_t* b) {
    asm volatile(
        "mma.sync.aligned.m16n8k8.row.col.f32.tf32.tf32.f32 "
        "{%0,%1,%2,%3}, {%4,%5,%6,%7}, {%8,%9}, {%0,%1,%2,%3};\n"
        : "+f"(d[0]), "+f"(d[1]), "+f"(d[2]), "+f"(d[3])
        : "r"(a[0]), "r"(a[1]), "r"(a[2]), "r"(a[3]), "r"(b[0]), "r"(b[1]));
}

__device__ __forceinline__ void mma_bf16(float* d, const uint32_t* a,
                                         uint32_t b0, uint32_t b1) {
    asm volatile(
        "mma.sync.aligned.m16n8k16.row.col.f32.bf16.bf16.f32 "
        "{%0,%1,%2,%3}, {%4,%5,%6,%7}, {%8,%9}, {%0,%1,%2,%3};\n"
        : "+f"(d[0]), "+f"(d[1]), "+f"(d[2]), "+f"(d[3])
        : "r"(a[0]), "r"(a[1]), "r"(a[2]), "r"(a[3]), "r"(b0), "r"(b1));
}

// split (x,y) into bf16 hi pair and bf16 lo (residual) pair; .x is low half
__device__ __forceinline__ void bsplit2(float x, float y, uint32_t& hi, uint32_t& lo) {
    __nv_bfloat162 H = __floats2bfloat162_rn(x, y);
    float rx = x - __bfloat162float(H.x);
    float ry = y - __bfloat162float(H.y);
    __nv_bfloat162 L = __floats2bfloat162_rn(rx, ry);
    hi = *reinterpret_cast<uint32_t*>(&H);
    lo = *reinterpret_cast<uint32_t*>(&L);
}

__device__ __forceinline__ float ex2(float x) {
    float r;
    asm("ex2.approx.ftz.f32 %0, %1;" : "=f"(r) : "f"(x));
    return r;
}

// ---------------------------------------------------------------------------
// tf32 tensor-core GEMM with fused bias (unchanged from R4)
// ---------------------------------------------------------------------------
#define GBM 128
#define GBN 128
#define GBK 16
#define APAD 4
#define BPAD 4

template <bool A_SCRATCH_ATTN, bool C_SCRATCH_QKV>
__global__ __launch_bounds__(256)
void gemm_tf32(int M, int N, int K,
               const float* __restrict__ Ain,
               const float* __restrict__ B,
               const float* __restrict__ bias,
               float* __restrict__ Cout) {
    const float* A = A_SCRATCH_ATTN ? g_attn : Ain;
    float* C = C_SCRATCH_QKV ? g_qkv : Cout;

    __shared__ float As[GBK][GBM + APAD];
    __shared__ float Bs[GBK][GBN + BPAD];

    const int tid  = threadIdx.x;
    const int warp = tid >> 5;
    const int lane = tid & 31;
    const int g    = lane >> 2;
    const int t4   = lane & 3;

    const int warpM = warp >> 2;
    const int warpN = warp & 3;

    const int blkM = blockIdx.y * GBM;
    const int blkN = blockIdx.x * GBN;

    const int rA = tid >> 2;
    const int cA = (tid & 3) * 4;
    const int rB = tid >> 5;
    const int cB = (tid & 31) * 4;

    float acc[4][4][4];
#pragma unroll
    for (int mi = 0; mi < 4; ++mi)
#pragma unroll
        for (int ni = 0; ni < 4; ++ni)
#pragma unroll
            for (int j = 0; j < 4; ++j) acc[mi][ni][j] = 0.f;

    for (int bk = 0; bk < K; bk += GBK) {
#pragma unroll
        for (int half = 0; half < 2; ++half) {
            int row = rA + half * 64;
            float4 a4 = *reinterpret_cast<const float4*>(&A[(size_t)(blkM + row) * K + bk + cA]);
            As[cA + 0][row] = f2tf32(a4.x);
            As[cA + 1][row] = f2tf32(a4.y);
            As[cA + 2][row] = f2tf32(a4.z);
            As[cA + 3][row] = f2tf32(a4.w);
        }
#pragma unroll
        for (int half = 0; half < 2; ++half) {
            int row = rB + half * 8;
            float4 b4 = *reinterpret_cast<const float4*>(&B[(size_t)(bk + row) * N + blkN + cB]);
            float4 t;
            t.x = f2tf32(b4.x); t.y = f2tf32(b4.y);
            t.z = f2tf32(b4.z); t.w = f2tf32(b4.w);
            *reinterpret_cast<float4*>(&Bs[row][cB]) = t;
        }
        __syncthreads();

#pragma unroll
        for (int ks = 0; ks < GBK; ks += 8) {
            uint32_t afrag[4][4];
#pragma unroll
            for (int mi = 0; mi < 4; ++mi) {
                int m0 = warpM * 64 + mi * 16 + g;
                afrag[mi][0] = __float_as_uint(As[ks + t4][m0]);
                afrag[mi][1] = __float_as_uint(As[ks + t4][m0 + 8]);
                afrag[mi][2] = __float_as_uint(As[ks + t4 + 4][m0]);
                afrag[mi][3] = __float_as_uint(As[ks + t4 + 4][m0 + 8]);
            }
            uint32_t bfrag[4][2];
#pragma unroll
            for (int ni = 0; ni < 4; ++ni) {
                int n0 = warpN * 32 + ni * 8 + g;
                bfrag[ni][0] = __float_as_uint(Bs[ks + t4][n0]);
                bfrag[ni][1] = __float_as_uint(Bs[ks + t4 + 4][n0]);
            }
#pragma unroll
            for (int mi = 0; mi < 4; ++mi)
#pragma unroll
                for (int ni = 0; ni < 4; ++ni)
                    mma_tf32(acc[mi][ni], afrag[mi], bfrag[ni]);
        }
        __syncthreads();
    }

#pragma unroll
    for (int mi = 0; mi < 4; ++mi) {
#pragma unroll
        for (int ni = 0; ni < 4; ++ni) {
            int row0 = blkM + warpM * 64 + mi * 16 + g;
            int col  = blkN + warpN * 32 + ni * 8 + 2 * t4;
            float2 b2 = *reinterpret_cast<const float2*>(&bias[col]);
            float2 r0, r1;
            r0.x = acc[mi][ni][0] + b2.x;
            r0.y = acc[mi][ni][1] + b2.y;
            r1.x = acc[mi][ni][2] + b2.x;
            r1.y = acc[mi][ni][3] + b2.y;
            *reinterpret_cast<float2*>(&C[(size_t)row0 * N + col]) = r0;
            *reinterpret_cast<float2*>(&C[(size_t)(row0 + 8) * N + col]) = r1;
        }
    }
}

// ---------------------------------------------------------------------------
// Tensor-core flash attention, bf16x3 (hi/lo split) for QK^T and P*V.
// Block: 128 threads = 4 warps; 64 q-rows per block (16 per warp), 64-key tiles.
// Smem: K as hd-pairs KP[key][hp], V as key-pairs VP[hd][kp], stride 36 u32
// (36 % 32 == 4 -> B-fragment reads conflict-free: bank = 4g + t4).
// ---------------------------------------------------------------------------
#define AST 36

__global__ __launch_bounds__(128)
void flash_attn_mma(const int* __restrict__ amask) {
    __shared__ uint32_t KPhi[64 * AST];
    __shared__ uint32_t KPlo[64 * AST];
    __shared__ uint32_t VPhi[64 * AST];
    __shared__ uint32_t VPlo[64 * AST];
    __shared__ int Ms[64];

    const int qb = (int)(gridDim.x - 1 - blockIdx.x);   // heavy blocks first
    const int h = blockIdx.y, b = blockIdx.z;
    const int tid = threadIdx.x;
    const int warp = tid >> 5, lane = tid & 31;
    const int g = lane >> 2, t4 = lane & 3;

    const size_t bbase = (size_t)b * SS * E3;
    const float* Qg = g_qkv + bbase + (size_t)h * HD;
    const float* Kg = g_qkv + bbase + EE + (size_t)h * HD;
    const float* Vg = g_qkv + bbase + 2 * EE + (size_t)h * HD;

    const int qrow0 = qb * 64 + warp * 16;
    const int r0 = qrow0 + g;
    const int r1 = r0 + 8;

    // ---- Q fragments: scaled by 1/sqrt(hd) * log2(e), split hi/lo ----
    const float qsc = 0.125f * 1.4426950408889634f;
    uint32_t Qhi[4][4], Qlo[4][4];
#pragma unroll
    for (int kf = 0; kf < 4; ++kf) {
        int hd0 = kf * 16 + 2 * t4;
        float2 x0 = *(const float2*)(Qg + (size_t)r0 * E3 + hd0);
        float2 x1 = *(const float2*)(Qg + (size_t)r1 * E3 + hd0);
        float2 x2 = *(const float2*)(Qg + (size_t)r0 * E3 + hd0 + 8);
        float2 x3 = *(const float2*)(Qg + (size_t)r1 * E3 + hd0 + 8);
        bsplit2(x0.x * qsc, x0.y * qsc, Qhi[kf][0], Qlo[kf][0]);
        bsplit2(x1.x * qsc, x1.y * qsc, Qhi[kf][1], Qlo[kf][1]);
        bsplit2(x2.x * qsc, x2.y * qsc, Qhi[kf][2], Qlo[kf][2]);
        bsplit2(x3.x * qsc, x3.y * qsc, Qhi[kf][3], Qlo[kf][3]);
    }

    float O[8][4];
#pragma unroll
    for (int nh = 0; nh < 8; ++nh)
#pragma unroll
        for (int j = 0; j < 4; ++j) O[nh][j] = 0.f;
    float m0 = -1e30f, m1 = -1e30f, l0 = 0.f, l1 = 0.f;

    for (int kt = 0; kt <= qb; ++kt) {
        const int k0 = kt * 64;

        // ---- K tile -> KP[key][hdpair] hi/lo ----
#pragma unroll
        for (int it = 0; it < 8; ++it) {
            int flat = it * 128 + tid;
            int key = flat >> 4, hd4 = flat & 15;
            float4 kx = *(const float4*)(Kg + (size_t)(k0 + key) * E3 + hd4 * 4);
            uint32_t h0, L0, h1, L1;
            bsplit2(kx.x, kx.y, h0, L0);
            bsplit2(kx.z, kx.w, h1, L1);
            KPhi[key * AST + 2 * hd4]     = h0;
            KPhi[key * AST + 2 * hd4 + 1] = h1;
            KPlo[key * AST + 2 * hd4]     = L0;
            KPlo[key * AST + 2 * hd4 + 1] = L1;
        }
        // ---- V tile -> VP[hd][keypair] hi/lo (transposed pack) ----
#pragma unroll
        for (int it = 0; it < 4; ++it) {
            int flat = it * 128 + tid;
            int kp = flat & 31, hd4 = flat >> 5;
            const float* va = Vg + (size_t)(k0 + 2 * kp) * E3 + hd4 * 4;
            float4 A4 = *(const float4*)va;
            float4 B4 = *(const float4*)(va + E3);
            uint32_t hh, ll;
            bsplit2(A4.x, B4.x, hh, ll);
            VPhi[(4 * hd4 + 0) * AST + kp] = hh; VPlo[(4 * hd4 + 0) * AST + kp] = ll;
            bsplit2(A4.y, B4.y, hh, ll);
            VPhi[(4 * hd4 + 1) * AST + kp] = hh; VPlo[(4 * hd4 + 1) * AST + kp] = ll;
            bsplit2(A4.z, B4.z, hh, ll);
            VPhi[(4 * hd4 + 2) * AST + kp] = hh; VPlo[(4 * hd4 + 2) * AST + kp] = ll;
            bsplit2(A4.w, B4.w, hh, ll);
            VPhi[(4 * hd4 + 3) * AST + kp] = hh; VPlo[(4 * hd4 + 3) * AST + kp] = ll;
        }
        if (tid < 64) Ms[tid] = amask[b * SS + k0 + tid];
        __syncthreads();

        // ---- S = Q K^T (bf16x3) ----
        float S[8][4];
#pragma unroll
        for (int nf = 0; nf < 8; ++nf)
#pragma unroll
            for (int j = 0; j < 4; ++j) S[nf][j] = 0.f;

#pragma unroll
        for (int nf = 0; nf < 8; ++nf) {
            const uint32_t* kh = &KPhi[(8 * nf + g) * AST];
            const uint32_t* kl = &KPlo[(8 * nf + g) * AST];
#pragma unroll
            for (int kf = 0; kf < 4; ++kf) {
                uint32_t b0h = kh[8 * kf + t4], b1h = kh[8 * kf + t4 + 4];
                uint32_t b0l = kl[8 * kf + t4], b1l = kl[8 * kf + t4 + 4];
                mma_bf16(S[nf], Qhi[kf], b0h, b1h);
                mma_bf16(S[nf], Qhi[kf], b0l, b1l);
                mma_bf16(S[nf], Qlo[kf], b0h, b1h);
            }
        }

        // ---- mask (causal on diagonal tile + padding everywhere) ----
        const bool diag = (kt == qb);
#pragma unroll
        for (int nf = 0; nf < 8; ++nf) {
            int cl = 8 * nf + 2 * t4;
            int col = k0 + cl;
            bool mv0 = Ms[cl] != 0;
            bool mv1 = Ms[cl + 1] != 0;
            if (!(mv0 && (!diag || col     <= r0))) S[nf][0] = -1e30f;
            if (!(mv1 && (!diag || col + 1 <= r0))) S[nf][1] = -1e30f;
            if (!(mv0 && (!diag || col     <= r1))) S[nf][2] = -1e30f;
            if (!(mv1 && (!diag || col + 1 <= r1))) S[nf][3] = -1e30f;
        }

        // ---- online softmax (base-2; scale folded into Q) ----
        float mx0 = -1e30f, mx1 = -1e30f;
#pragma unroll
        for (int nf = 0; nf < 8; ++nf) {
            mx0 = fmaxf(mx0, fmaxf(S[nf][0], S[nf][1]));
            mx1 = fmaxf(mx1, fmaxf(S[nf][2], S[nf][3]));
        }
        mx0 = fmaxf(mx0, __shfl_xor_sync(0xFFFFFFFFu, mx0, 1));
        mx0 = fmaxf(mx0, __shfl_xor_sync(0xFFFFFFFFu, mx0, 2));
        mx1 = fmaxf(mx1, __shfl_xor_sync(0xFFFFFFFFu, mx1, 1));
        mx1 = fmaxf(mx1, __shfl_xor_sync(0xFFFFFFFFu, mx1, 2));
        float mn0 = fmaxf(fmaxf(m0, mx0), -8e29f);
        float mn1 = fmaxf(fmaxf(m1, mx1), -8e29f);
        float al0 = ex2(m0 - mn0);
        float al1 = ex2(m1 - mn1);
        float s0 = 0.f, s1 = 0.f;
#pragma unroll
        for (int nf = 0; nf < 8; ++nf) {
            S[nf][0] = ex2(S[nf][0] - mn0); s0 += S[nf][0];
            S[nf][1] = ex2(S[nf][1] - mn0); s0 += S[nf][1];
            S[nf][2] = ex2(S[nf][2] - mn1); s1 += S[nf][2];
            S[nf][3] = ex2(S[nf][3] - mn1); s1 += S[nf][3];
        }
        s0 += __shfl_xor_sync(0xFFFFFFFFu, s0, 1);
        s0 += __shfl_xor_sync(0xFFFFFFFFu, s0, 2);
        s1 += __shfl_xor_sync(0xFFFFFFFFu, s1, 1);
        s1 += __shfl_xor_sync(0xFFFFFFFFu, s1, 2);
        l0 = l0 * al0 + s0;
        l1 = l1 * al1 + s1;
        m0 = mn0; m1 = mn1;
#pragma unroll
        for (int nh = 0; nh < 8; ++nh) {
            O[nh][0] *= al0; O[nh][1] *= al0;
            O[nh][2] *= al1; O[nh][3] *= al1;
        }

        // ---- O += P V  (P converted to A-frags in registers, bf16x3) ----
#pragma unroll
        for (int kf = 0; kf < 4; ++kf) {
            uint32_t ah[4], al[4];
            bsplit2(S[2 * kf][0],     S[2 * kf][1],     ah[0], al[0]);
            bsplit2(S[2 * kf][2],     S[2 * kf][3],     ah[1], al[1]);
            bsplit2(S[2 * kf + 1][0], S[2 * kf + 1][1], ah[2], al[2]);
            bsplit2(S[2 * kf + 1][2], S[2 * kf + 1][3], ah[3], al[3]);
#pragma unroll
            for (int nh = 0; nh < 8; ++nh) {
                const uint32_t* vh = &VPhi[(8 * nh + g) * AST];
                const uint32_t* vl = &VPlo[(8 * nh + g) * AST];
                uint32_t b0h = vh[8 * kf + t4], b1h = vh[8 * kf + t4 + 4];
                uint32_t b0l = vl[8 * kf + t4], b1l = vl[8 * kf + t4 + 4];
                mma_bf16(O[nh], ah, b0h, b1h);
                mma_bf16(O[nh], ah, b0l, b1l);
                mma_bf16(O[nh], al, b0h, b1h);
            }
        }
        __syncthreads();   // protect KP/VP/Ms before next tile overwrite
    }

    // ---- epilogue: normalize, write g_attn[b, row, h*HD + col] ----
    const float inv0 = 1.0f / l0;
    const float inv1 = 1.0f / l1;
    float* outp = g_attn + (size_t)b * SS * EE + (size_t)h * HD;
#pragma unroll
    for (int nh = 0; nh < 8; ++nh) {
        int col = 8 * nh + 2 * t4;
        float2 w0, w1;
        w0.x = O[nh][0] * inv0; w0.y = O[nh][1] * inv0;
        w1.x = O[nh][2] * inv1; w1.y = O[nh][3] * inv1;
        *(float2*)(outp + (size_t)r0 * EE + col) = w0;
        *(float2*)(outp + (size_t)r1 * EE + col) = w1;
    }
}

// ---------------------------------------------------------------------------
// Launch — ONLY kernel launches
// ---------------------------------------------------------------------------
extern "C" void kernel_launch(void* const* d_in, const int* in_sizes, int n_in,
                              void* d_out, int out_size) {
    const float* x      = (const float*)d_in[0];
    const int*   amask  = (const int*)d_in[1];
    const float* W_attn = (const float*)d_in[2];
    const float* b_attn = (const float*)d_in[3];
    const float* W_proj = (const float*)d_in[4];
    const float* b_proj = (const float*)d_in[5];
    float* out = (float*)d_out;

    // 1) QKV projection: [8192,1024] @ [1024,3072] + bias -> g_qkv
    {
        dim3 grid(E3 / GBN, (BB * SS) / GBM);
        gemm_tf32<false, true><<<grid, 256>>>(BB * SS, E3, EE, x, W_attn, b_attn, nullptr);
    }
    // 2) Attention: g_qkv -> g_attn
    {
        dim3 grid(SS / 64, HH, BB);
        flash_attn_mma<<<grid, 128>>>(amask);
    }
    // 3) Output projection: [8192,1024] @ [1024,1024] + bias -> d_out
    {
        dim3 grid(EE / GBN, (BB * SS) / GBM);
        gemm_tf32<true, false><<<grid, 256>>>(BB * SS, EE, EE, nullptr, W_proj, b_proj, out);
    }
}

// round 6
// speedup vs baseline: 6.5197x; 1.2735x over previous
#include <cuda_runtime.h>
#include <cuda_bf16.h>
#include <cstdint>

// Problem constants
#define BB 4
#define SS 2048
#define EE 1024
#define HH 16
#define HD 64
#define E3 (3 * EE)

// Scratch (alloc-free requirement -> __device__ globals)
__device__ float g_qkv[BB * SS * E3];      // [b, s, 3E]  (~100 MB)
__device__ float g_attn[BB * SS * EE];     // [b, s, E]   (~33 MB)

// ---------------------------------------------------------------------------
// helpers
// ---------------------------------------------------------------------------
__device__ __forceinline__ float f2tf32(float x) {
    uint32_t u;
    asm("cvt.rna.tf32.f32 %0, %1;" : "=r"(u) : "f"(x));
    return __uint_as_float(u);
}

__device__ __forceinline__ void mma_tf32(float* d, const uint32_t* a, const uint32_t* b) {
    asm volatile(
        "mma.sync.aligned.m16n8k8.row.col.f32.tf32.tf32.f32 "
        "{%0,%1,%2,%3}, {%4,%5,%6,%7}, {%8,%9}, {%0,%1,%2,%3};\n"
        : "+f"(d[0]), "+f"(d[1]), "+f"(d[2]), "+f"(d[3])
        : "r"(a[0]), "r"(a[1]), "r"(a[2]), "r"(a[3]), "r"(b[0]), "r"(b[1]));
}

__device__ __forceinline__ void mma_bf16(float* d, const uint32_t* a,
                                         uint32_t b0, uint32_t b1) {
    asm volatile(
        "mma.sync.aligned.m16n8k16.row.col.f32.bf16.bf16.f32 "
        "{%0,%1,%2,%3}, {%4,%5,%6,%7}, {%8,%9}, {%0,%1,%2,%3};\n"
        : "+f"(d[0]), "+f"(d[1]), "+f"(d[2]), "+f"(d[3])
        : "r"(a[0]), "r"(a[1]), "r"(a[2]), "r"(a[3]), "r"(b0), "r"(b1));
}

__device__ __forceinline__ void bsplit2(float x, float y, uint32_t& hi, uint32_t& lo) {
    __nv_bfloat162 H = __floats2bfloat162_rn(x, y);
    float rx = x - __bfloat162float(H.x);
    float ry = y - __bfloat162float(H.y);
    __nv_bfloat162 L = __floats2bfloat162_rn(rx, ry);
    hi = *reinterpret_cast<uint32_t*>(&H);
    lo = *reinterpret_cast<uint32_t*>(&L);
}

__device__ __forceinline__ float ex2(float x) {
    float r;
    asm("ex2.approx.ftz.f32 %0, %1;" : "=f"(r) : "f"(x));
    return r;
}

// ---------------------------------------------------------------------------
// tf32 tensor-core GEMM, pipelined, ldmatrix A feed, conflict-free B feed.
// C[M,N] = A[M,K] @ B[K,N] + bias[N].  BM=BN=128, BK=16, 256 thr = 8 warps.
// As: [m][k] stride 20 (ldmatrix conflict-free); Bs: [k][n] stride 136 (≡8 mod 32).
// ---------------------------------------------------------------------------
#define GBM 128
#define GBN 128
#define GBK 16
#define ASTRIDE (GBK + 4)    // 20 floats
#define BSTRIDE (GBN + 8)    // 136 floats

template <bool A_SCRATCH_ATTN, bool C_SCRATCH_QKV>
__global__ __launch_bounds__(256, 2)
void gemm_tf32(int M, int N, int K,
               const float* __restrict__ Ain,
               const float* __restrict__ B,
               const float* __restrict__ bias,
               float* __restrict__ Cout) {
    const float* A = A_SCRATCH_ATTN ? g_attn : Ain;
    float* C = C_SCRATCH_QKV ? g_qkv : Cout;

    __shared__ float As[2][GBM * ASTRIDE];
    __shared__ float Bs[2][GBK * BSTRIDE];

    const int tid  = threadIdx.x;
    const int warp = tid >> 5;
    const int lane = tid & 31;
    const int g    = lane >> 2;
    const int t4   = lane & 3;
    const int warpM = warp >> 2;
    const int warpN = warp & 3;
    const int blkM = blockIdx.y * GBM;
    const int blkN = blockIdx.x * GBN;

    const int rA = tid >> 2;          // 0..63 (+64)
    const int cA = (tid & 3) * 4;
    const int rB = tid >> 5;          // 0..7 (+8)
    const int cB = (tid & 31) * 4;

    const int nt = K / GBK;

    float4 a4[2], b4[2];

    // prefetch tile 0
    a4[0] = *(const float4*)&A[(size_t)(blkM + rA) * K + cA];
    a4[1] = *(const float4*)&A[(size_t)(blkM + rA + 64) * K + cA];
    b4[0] = *(const float4*)&B[(size_t)rB * N + blkN + cB];
    b4[1] = *(const float4*)&B[(size_t)(rB + 8) * N + blkN + cB];

    auto store_tile = [&](int buf) {
        float* as = As[buf];
        float* bs = Bs[buf];
#pragma unroll
        for (int hh = 0; hh < 2; ++hh) {
            float4 t;
            t.x = f2tf32(a4[hh].x); t.y = f2tf32(a4[hh].y);
            t.z = f2tf32(a4[hh].z); t.w = f2tf32(a4[hh].w);
            *(float4*)&as[(rA + hh * 64) * ASTRIDE + cA] = t;
            float4 u;
            u.x = f2tf32(b4[hh].x); u.y = f2tf32(b4[hh].y);
            u.z = f2tf32(b4[hh].z); u.w = f2tf32(b4[hh].w);
            *(float4*)&bs[(rB + hh * 8) * BSTRIDE + cB] = u;
        }
    };
    store_tile(0);
    __syncthreads();

    float acc[4][4][4];
#pragma unroll
    for (int mi = 0; mi < 4; ++mi)
#pragma unroll
        for (int ni = 0; ni < 4; ++ni)
#pragma unroll
            for (int j = 0; j < 4; ++j) acc[mi][ni][j] = 0.f;

    // ldmatrix per-thread source row/col (within the warp tile)
    const int lm_row = lane & 15;             // row offset within 16-row frag
    const int lm_kof = (lane >> 4) << 2;      // 0 or 4 (k offset)

    for (int bk = 0; bk < nt; ++bk) {
        const int cur = bk & 1;
        if (bk + 1 < nt) {
            const int off = (bk + 1) * GBK;
            a4[0] = *(const float4*)&A[(size_t)(blkM + rA) * K + off + cA];
            a4[1] = *(const float4*)&A[(size_t)(blkM + rA + 64) * K + off + cA];
            b4[0] = *(const float4*)&B[(size_t)(off + rB) * N + blkN + cB];
            b4[1] = *(const float4*)&B[(size_t)(off + rB + 8) * N + blkN + cB];
        }
        const float* as = As[cur];
        const float* bs = Bs[cur];
#pragma unroll
        for (int ks = 0; ks < GBK; ks += 8) {
            uint32_t bfrag[4][2];
#pragma unroll
            for (int ni = 0; ni < 4; ++ni) {
                int n0 = warpN * 32 + ni * 8 + g;
                bfrag[ni][0] = __float_as_uint(bs[(ks + t4) * BSTRIDE + n0]);
                bfrag[ni][1] = __float_as_uint(bs[(ks + t4 + 4) * BSTRIDE + n0]);
            }
#pragma unroll
            for (int mi = 0; mi < 4; ++mi) {
                const int m0 = warpM * 64 + mi * 16;
                uint32_t af[4];
                uint32_t addr = (uint32_t)__cvta_generic_to_shared(
                    &as[(m0 + lm_row) * ASTRIDE + ks + lm_kof]);
                asm volatile(
                    "ldmatrix.sync.aligned.m8n8.x4.shared.b16 {%0,%1,%2,%3}, [%4];"
                    : "=r"(af[0]), "=r"(af[1]), "=r"(af[2]), "=r"(af[3])
                    : "r"(addr));
#pragma unroll
                for (int ni = 0; ni < 4; ++ni)
                    mma_tf32(acc[mi][ni], af, bfrag[ni]);
            }
        }
        if (bk + 1 < nt) store_tile(cur ^ 1);
        __syncthreads();
    }

    // epilogue: bias + store
#pragma unroll
    for (int mi = 0; mi < 4; ++mi) {
#pragma unroll
        for (int ni = 0; ni < 4; ++ni) {
            int row0 = blkM + warpM * 64 + mi * 16 + g;
            int col  = blkN + warpN * 32 + ni * 8 + 2 * t4;
            float2 b2 = *reinterpret_cast<const float2*>(&bias[col]);
            float2 r0, r1;
            r0.x = acc[mi][ni][0] + b2.x;
            r0.y = acc[mi][ni][1] + b2.y;
            r1.x = acc[mi][ni][2] + b2.x;
            r1.y = acc[mi][ni][3] + b2.y;
            *reinterpret_cast<float2*>(&C[(size_t)row0 * N + col]) = r0;
            *reinterpret_cast<float2*>(&C[(size_t)(row0 + 8) * N + col]) = r1;
        }
    }
}

// ---------------------------------------------------------------------------
// Tensor-core flash attention, bf16x3 (unchanged from R5, known-good).
// ---------------------------------------------------------------------------
#define AST 36

__global__ __launch_bounds__(128)
void flash_attn_mma(const int* __restrict__ amask) {
    __shared__ uint32_t KPhi[64 * AST];
    __shared__ uint32_t KPlo[64 * AST];
    __shared__ uint32_t VPhi[64 * AST];
    __shared__ uint32_t VPlo[64 * AST];
    __shared__ int Ms[64];

    const int qb = (int)(gridDim.x - 1 - blockIdx.x);   // heavy blocks first
    const int h = blockIdx.y, b = blockIdx.z;
    const int tid = threadIdx.x;
    const int warp = tid >> 5, lane = tid & 31;
    const int g = lane >> 2, t4 = lane & 3;

    const size_t bbase = (size_t)b * SS * E3;
    const float* Qg = g_qkv + bbase + (size_t)h * HD;
    const float* Kg = g_qkv + bbase + EE + (size_t)h * HD;
    const float* Vg = g_qkv + bbase + 2 * EE + (size_t)h * HD;

    const int qrow0 = qb * 64 + warp * 16;
    const int r0 = qrow0 + g;
    const int r1 = r0 + 8;

    const float qsc = 0.125f * 1.4426950408889634f;
    uint32_t Qhi[4][4], Qlo[4][4];
#pragma unroll
    for (int kf = 0; kf < 4; ++kf) {
        int hd0 = kf * 16 + 2 * t4;
        float2 x0 = *(const float2*)(Qg + (size_t)r0 * E3 + hd0);
        float2 x1 = *(const float2*)(Qg + (size_t)r1 * E3 + hd0);
        float2 x2 = *(const float2*)(Qg + (size_t)r0 * E3 + hd0 + 8);
        float2 x3 = *(const float2*)(Qg + (size_t)r1 * E3 + hd0 + 8);
        bsplit2(x0.x * qsc, x0.y * qsc, Qhi[kf][0], Qlo[kf][0]);
        bsplit2(x1.x * qsc, x1.y * qsc, Qhi[kf][1], Qlo[kf][1]);
        bsplit2(x2.x * qsc, x2.y * qsc, Qhi[kf][2], Qlo[kf][2]);
        bsplit2(x3.x * qsc, x3.y * qsc, Qhi[kf][3], Qlo[kf][3]);
    }

    float O[8][4];
#pragma unroll
    for (int nh = 0; nh < 8; ++nh)
#pragma unroll
        for (int j = 0; j < 4; ++j) O[nh][j] = 0.f;
    float m0 = -1e30f, m1 = -1e30f, l0 = 0.f, l1 = 0.f;

    for (int kt = 0; kt <= qb; ++kt) {
        const int k0 = kt * 64;

#pragma unroll
        for (int it = 0; it < 8; ++it) {
            int flat = it * 128 + tid;
            int key = flat >> 4, hd4 = flat & 15;
            float4 kx = *(const float4*)(Kg + (size_t)(k0 + key) * E3 + hd4 * 4);
            uint32_t h0, L0, h1, L1;
            bsplit2(kx.x, kx.y, h0, L0);
            bsplit2(kx.z, kx.w, h1, L1);
            KPhi[key * AST + 2 * hd4]     = h0;
            KPhi[key * AST + 2 * hd4 + 1] = h1;
            KPlo[key * AST + 2 * hd4]     = L0;
            KPlo[key * AST + 2 * hd4 + 1] = L1;
        }
#pragma unroll
        for (int it = 0; it < 4; ++it) {
            int flat = it * 128 + tid;
            int kp = flat & 31, hd4 = flat >> 5;
            const float* va = Vg + (size_t)(k0 + 2 * kp) * E3 + hd4 * 4;
            float4 A4 = *(const float4*)va;
            float4 B4 = *(const float4*)(va + E3);
            uint32_t hh, ll;
            bsplit2(A4.x, B4.x, hh, ll);
            VPhi[(4 * hd4 + 0) * AST + kp] = hh; VPlo[(4 * hd4 + 0) * AST + kp] = ll;
            bsplit2(A4.y, B4.y, hh, ll);
            VPhi[(4 * hd4 + 1) * AST + kp] = hh; VPlo[(4 * hd4 + 1) * AST + kp] = ll;
            bsplit2(A4.z, B4.z, hh, ll);
            VPhi[(4 * hd4 + 2) * AST + kp] = hh; VPlo[(4 * hd4 + 2) * AST + kp] = ll;
            bsplit2(A4.w, B4.w, hh, ll);
            VPhi[(4 * hd4 + 3) * AST + kp] = hh; VPlo[(4 * hd4 + 3) * AST + kp] = ll;
        }
        if (tid < 64) Ms[tid] = amask[b * SS + k0 + tid];
        __syncthreads();

        float S[8][4];
#pragma unroll
        for (int nf = 0; nf < 8; ++nf)
#pragma unroll
            for (int j = 0; j < 4; ++j) S[nf][j] = 0.f;

#pragma unroll
        for (int nf = 0; nf < 8; ++nf) {
            const uint32_t* kh = &KPhi[(8 * nf + g) * AST];
            const uint32_t* kl = &KPlo[(8 * nf + g) * AST];
#pragma unroll
            for (int kf = 0; kf < 4; ++kf) {
                uint32_t b0h = kh[8 * kf + t4], b1h = kh[8 * kf + t4 + 4];
                uint32_t b0l = kl[8 * kf + t4], b1l = kl[8 * kf + t4 + 4];
                mma_bf16(S[nf], Qhi[kf], b0h, b1h);
                mma_bf16(S[nf], Qhi[kf], b0l, b1l);
                mma_bf16(S[nf], Qlo[kf], b0h, b1h);
            }
        }

        const bool diag = (kt == qb);
#pragma unroll
        for (int nf = 0; nf < 8; ++nf) {
            int cl = 8 * nf + 2 * t4;
            int col = k0 + cl;
            bool mv0 = Ms[cl] != 0;
            bool mv1 = Ms[cl + 1] != 0;
            if (!(mv0 && (!diag || col     <= r0))) S[nf][0] = -1e30f;
            if (!(mv1 && (!diag || col + 1 <= r0))) S[nf][1] = -1e30f;
            if (!(mv0 && (!diag || col     <= r1))) S[nf][2] = -1e30f;
            if (!(mv1 && (!diag || col + 1 <= r1))) S[nf][3] = -1e30f;
        }

        float mx0 = -1e30f, mx1 = -1e30f;
#pragma unroll
        for (int nf = 0; nf < 8; ++nf) {
            mx0 = fmaxf(mx0, fmaxf(S[nf][0], S[nf][1]));
            mx1 = fmaxf(mx1, fmaxf(S[nf][2], S[nf][3]));
        }
        mx0 = fmaxf(mx0, __shfl_xor_sync(0xFFFFFFFFu, mx0, 1));
        mx0 = fmaxf(mx0, __shfl_xor_sync(0xFFFFFFFFu, mx0, 2));
        mx1 = fmaxf(mx1, __shfl_xor_sync(0xFFFFFFFFu, mx1, 1));
        mx1 = fmaxf(mx1, __shfl_xor_sync(0xFFFFFFFFu, mx1, 2));
        float mn0 = fmaxf(fmaxf(m0, mx0), -8e29f);
        float mn1 = fmaxf(fmaxf(m1, mx1), -8e29f);
        float al0 = ex2(m0 - mn0);
        float al1 = ex2(m1 - mn1);
        float s0 = 0.f, s1 = 0.f;
#pragma unroll
        for (int nf = 0; nf < 8; ++nf) {
            S[nf][0] = ex2(S[nf][0] - mn0); s0 += S[nf][0];
            S[nf][1] = ex2(S[nf][1] - mn0); s0 += S[nf][1];
            S[nf][2] = ex2(S[nf][2] - mn1); s1 += S[nf][2];
            S[nf][3] = ex2(S[nf][3] - mn1); s1 += S[nf][3];
        }
        s0 += __shfl_xor_sync(0xFFFFFFFFu, s0, 1);
        s0 += __shfl_xor_sync(0xFFFFFFFFu, s0, 2);
        s1 += __shfl_xor_sync(0xFFFFFFFFu, s1, 1);
        s1 += __shfl_xor_sync(0xFFFFFFFFu, s1, 2);
        l0 = l0 * al0 + s0;
        l1 = l1 * al1 + s1;
        m0 = mn0; m1 = mn1;
#pragma unroll
        for (int nh = 0; nh < 8; ++nh) {
            O[nh][0] *= al0; O[nh][1] *= al0;
            O[nh][2] *= al1; O[nh][3] *= al1;
        }

#pragma unroll
        for (int kf = 0; kf < 4; ++kf) {
            uint32_t ah[4], al[4];
            bsplit2(S[2 * kf][0],     S[2 * kf][1],     ah[0], al[0]);
            bsplit2(S[2 * kf][2],     S[2 * kf][3],     ah[1], al[1]);
            bsplit2(S[2 * kf + 1][0], S[2 * kf + 1][1], ah[2], al[2]);
            bsplit2(S[2 * kf + 1][2], S[2 * kf + 1][3], ah[3], al[3]);
#pragma unroll
            for (int nh = 0; nh < 8; ++nh) {
                const uint32_t* vh = &VPhi[(8 * nh + g) * AST];
                const uint32_t* vl = &VPlo[(8 * nh + g) * AST];
                uint32_t b0h = vh[8 * kf + t4], b1h = vh[8 * kf + t4 + 4];
                uint32_t b0l = vl[8 * kf + t4], b1l = vl[8 * kf + t4 + 4];
                mma_bf16(O[nh], ah, b0h, b1h);
                mma_bf16(O[nh], ah, b0l, b1l);
                mma_bf16(O[nh], al, b0h, b1h);
            }
        }
        __syncthreads();
    }

    const float inv0 = 1.0f / l0;
    const float inv1 = 1.0f / l1;
    float* outp = g_attn + (size_t)b * SS * EE + (size_t)h * HD;
#pragma unroll
    for (int nh = 0; nh < 8; ++nh) {
        int col = 8 * nh + 2 * t4;
        float2 w0, w1;
        w0.x = O[nh][0] * inv0; w0.y = O[nh][1] * inv0;
        w1.x = O[nh][2] * inv1; w1.y = O[nh][3] * inv1;
        *(float2*)(outp + (size_t)r0 * EE + col) = w0;
        *(float2*)(outp + (size_t)r1 * EE + col) = w1;
    }
}

// ---------------------------------------------------------------------------
// Launch — ONLY kernel launches
// ---------------------------------------------------------------------------
extern "C" void kernel_launch(void* const* d_in, const int* in_sizes, int n_in,
                              void* d_out, int out_size) {
    const float* x      = (const float*)d_in[0];
    const int*   amask  = (const int*)d_in[1];
    const float* W_attn = (const float*)d_in[2];
    const float* b_attn = (const float*)d_in[3];
    const float* W_proj = (const float*)d_in[4];
    const float* b_proj = (const float*)d_in[5];
    float* out = (float*)d_out;

    // 1) QKV projection: [8192,1024] @ [1024,3072] + bias -> g_qkv
    {
        dim3 grid(E3 / GBN, (BB * SS) / GBM);
        gemm_tf32<false, true><<<grid, 256>>>(BB * SS, E3, EE, x, W_attn, b_attn, nullptr);
    }
    // 2) Attention: g_qkv -> g_attn
    {
        dim3 grid(SS / 64, HH, BB);
        flash_attn_mma<<<grid, 128>>>(amask);
    }
    // 3) Output projection: [8192,1024] @ [1024,1024] + bias -> d_out
    {
        dim3 grid(EE / GBN, (BB * SS) / GBM);
        gemm_tf32<true, false><<<grid, 256>>>(BB * SS, EE, EE, nullptr, W_proj, b_proj, out);
    }
}